// round 6
// baseline (speedup 1.0000x reference)
#include <cuda_runtime.h>
#include <math_constants.h>

#define NT 32
#define NQ 256
#define NNODE 8192
#define DD 128
#define CHN 32
#define KK 16
#define NBF 8
#define BB 4
#define CAP 4096      // restored from R1 (proven); R4/R5's 2304 is the prime failure suspect
#define NTG 8         // t-groups
#define TPT 4         // transforms per block (NTG*TPT = NT)

__device__ float g_nfext[NNODE * DD];     // node_feature @ W_ext
__device__ float g_tf[DD];                // 1 + time_emb @ W_time
__device__ int   g_range[BB + 1];         // batch ranges in sorted node_batch
__device__ float g_coef[6 * CHN];         // folded dtp coefs: lin(a,b,e), ang(a,b,e)
__device__ float g_partial[NT * NQ * 6];  // per-(t,q) partials: ang3, lin3

static __device__ __forceinline__ unsigned long long umin64(unsigned long long a, unsigned long long b) {
    return a < b ? a : b;
}

static __device__ __forceinline__ float3 qrot(float w, float x, float y, float z, float3 v) {
    float uvx = y * v.z - z * v.y;
    float uvy = z * v.x - x * v.z;
    float uvz = x * v.y - y * v.x;
    float wx = y * uvz - z * uvy;
    float wy = z * uvx - x * uvz;
    float wz = x * uvy - y * uvx;
    float3 r;
    r.x = v.x + 2.f * (w * uvx + wx);
    r.y = v.y + 2.f * (w * uvy + wy);
    r.z = v.z + 2.f * (w * uvz + wz);
    return r;
}

// ---- precompute: nf_ext (blocked GEMM, R1-bit-exact order) + misc ------------
__global__ __launch_bounds__(DD) void k_pre(
    const float* __restrict__ nf, const float* __restrict__ Wext,
    const float* __restrict__ te, const float* __restrict__ Wtime,
    const int* __restrict__ nbatch,
    const float* __restrict__ wp_lin, const float* __restrict__ Wv_lin,
    const float* __restrict__ wp_ang, const float* __restrict__ Wv_ang) {
    int tid = threadIdx.x;
    if (blockIdx.x == NNODE / 16) {
        {
            float acc = 0.f;
            for (int k = 0; k < DD; k++) acc = fmaf(te[k], Wtime[k * DD + tid], acc);
            g_tf[tid] = 1.f + acc;
        }
        if (tid <= BB) {
            int lo = 0, hi = NNODE;
            if (tid == BB) lo = NNODE;
            else {
                while (lo < hi) { int m = (lo + hi) >> 1; if (nbatch[m] < tid) lo = m + 1; else hi = m; }
            }
            g_range[tid] = lo;
        }
        if (tid < CHN) {
            for (int g = 0; g < 6; g++) {
                const float* wp = (g < 3) ? wp_lin : wp_ang;
                const float* Wv = (g < 3) ? Wv_lin : Wv_ang;
                int gg = g % 3;
                int wrow = gg * CHN + tid;
                float s = 0.f;
                for (int o = 0; o < CHN; o++) s += Wv[wrow * CHN + o];
                g_coef[g * CHN + tid] = wp[(2 + gg) * CHN + tid] * s * (1.f / (float)CHN);
            }
        }
        return;
    }
    __shared__ float snf[16][DD];
    int b = blockIdx.x;
#pragma unroll
    for (int r = 0; r < 16; r++) snf[r][tid] = nf[(b * 16 + r) * DD + tid];
    __syncthreads();
    float acc[16];
#pragma unroll
    for (int n2 = 0; n2 < 16; n2++) acc[n2] = 0.f;
    for (int k = 0; k < DD; k += 4) {
        float w0 = Wext[(k + 0) * DD + tid];
        float w1 = Wext[(k + 1) * DD + tid];
        float w2 = Wext[(k + 2) * DD + tid];
        float w3 = Wext[(k + 3) * DD + tid];
#pragma unroll
        for (int n2 = 0; n2 < 16; n2++) {
            // ascending-k sequential accumulation: bit-identical to R1's k_nfext
            float a = acc[n2];
            a = fmaf(snf[n2][k + 0], w0, a);
            a = fmaf(snf[n2][k + 1], w1, a);
            a = fmaf(snf[n2][k + 2], w2, a);
            a = fmaf(snf[n2][k + 3], w3, a);
            acc[n2] = a;
        }
    }
#pragma unroll
    for (int n2 = 0; n2 < 16; n2++) g_nfext[(b * 16 + n2) * DD + tid] = acc[n2];
}

// ---- main: one block per (query, group of TPT transforms) --------------------
__global__ __launch_bounds__(256) void k_main(
    const float* __restrict__ T, const float* __restrict__ qwgt,
    const float* __restrict__ qf, const float* __restrict__ qcrd,
    const float* __restrict__ ncoord, const float* __restrict__ Wrbf,
    const int* __restrict__ qbatch) {
    __shared__ float sd2[CAP];                 // thread-private by construction (i = tid mod 256)
    __shared__ unsigned long long swmin[8];
    __shared__ unsigned long long sext;
    __shared__ float srbf[KK * NBF];
    __shared__ float sfield[DD];
    __shared__ int ssel[KK];
    __shared__ float sd2sel[KK];

    int qi = blockIdx.x, tg = blockIdx.y, tid = threadIdx.x;
    int lane = tid & 31, wid = tid >> 5;

    int b = qbatch[qi];
    int lo = g_range[b];
    int n = g_range[b + 1] - lo;
    if (n > CAP) n = CAP;
    float3 qc0 = { qcrd[qi * 3 + 0], qcrd[qi * 3 + 1], qcrd[qi * 3 + 2] };

    // warp0 preloads t-invariant epilogue state
    float e_s = 0.f, e_vx = 0.f, e_vy = 0.f, e_vz = 0.f;
    float e_al = 0.f, e_bl = 0.f, e_el = 0.f, e_aa = 0.f, e_ba = 0.f, e_ea = 0.f, e_w = 0.f;
    if (tid < CHN) {
        e_s  = qf[qi * DD + tid];
        e_vx = qf[qi * DD + CHN + 3 * tid + 0];
        e_vy = qf[qi * DD + CHN + 3 * tid + 1];
        e_vz = qf[qi * DD + CHN + 3 * tid + 2];
        e_al = g_coef[tid];           e_bl = g_coef[CHN + tid];     e_el = g_coef[2 * CHN + tid];
        e_aa = g_coef[3 * CHN + tid]; e_ba = g_coef[4 * CHN + tid]; e_ea = g_coef[5 * CHN + tid];
        e_w  = qwgt[qi];
    }

    for (int tt = 0; tt < TPT; tt++) {
        int t = tg * TPT + tt;
        float qw0 = T[t * 7 + 0], qx = T[t * 7 + 1], qy = T[t * 7 + 2], qz = T[t * 7 + 3];
        float3 p = qrot(qw0, qx, qy, qz, qc0);
        p.x += T[t * 7 + 4]; p.y += T[t * 7 + 5]; p.z += T[t * 7 + 6];

        // distance pass (global ncoord reads, exactly R1's expression/order)
        unsigned long long tm = ~0ull;
        for (int i = tid; i < n; i += 256) {
            float dx = p.x - ncoord[(lo + i) * 3 + 0];
            float dy = p.y - ncoord[(lo + i) * 3 + 1];
            float dz = p.z - ncoord[(lo + i) * 3 + 2];
            float d2 = dx * dx + dy * dy + dz * dz;
            sd2[i] = d2;
            unsigned long long key = ((unsigned long long)__float_as_uint(d2) << 32) | (unsigned)i;
            tm = umin64(tm, key);
        }

        // exact top-KK: 16 rounds of block-min extraction, 2 barriers/round
        for (int r = 0; r < KK; r++) {
            unsigned long long v = tm;
#pragma unroll
            for (int o = 16; o > 0; o >>= 1)
                v = umin64(v, __shfl_down_sync(0xffffffffu, v, o));
            if (lane == 0) swmin[wid] = v;
            __syncthreads();
            if (wid == 0) {
                unsigned long long v2 = (lane < 8) ? swmin[lane] : ~0ull;
#pragma unroll
                for (int o = 4; o > 0; o >>= 1)
                    v2 = umin64(v2, __shfl_down_sync(0xffffffffu, v2, o));
                if (lane == 0) sext = v2;
            }
            __syncthreads();
            unsigned long long w = sext;
            if (tid == 0) {
                ssel[r] = (int)(unsigned)w;
                sd2sel[r] = __uint_as_float((unsigned)(w >> 32));
            }
            if (w == tm) {
                // owner: remove extracted element, rescan own strided elements
                unsigned pos = (unsigned)w;
                sd2[pos] = CUDART_INF_F;
                tm = ~0ull;
                for (int i = tid; i < n; i += 256) {
                    unsigned long long key = ((unsigned long long)__float_as_uint(sd2[i]) << 32) | (unsigned)i;
                    tm = umin64(tm, key);
                }
            }
        }
        __syncthreads();

        // rbf basis for the 16 selected
        if (tid < KK * NBF) {
            int k = tid >> 3, bb2 = tid & 7;
            float d = sqrtf(fmaxf(sd2sel[k], 1e-12f));
            float e = d - (3.0f / 7.0f) * (float)bb2;
            srbf[tid] = expf(-4.f * e * e);
        }
        __syncthreads();

        // field[d] = tf[d] * sum_k (rbf[k] @ W_rbf)[d] * nf_ext[idx_k][d]
        if (tid < DD) {
            float acc = 0.f;
#pragma unroll
            for (int k = 0; k < KK; k++) {
                int gi = lo + ssel[k];
                float coef = 0.f;
#pragma unroll
                for (int bb2 = 0; bb2 < NBF; bb2++)
                    coef = fmaf(srbf[k * NBF + bb2], Wrbf[bb2 * DD + tid], coef);
                acc = fmaf(coef, g_nfext[gi * DD + tid], acc);
            }
            sfield[tid] = acc * g_tf[tid];
        }
        __syncthreads();

        // dtp + per-(t,q) partial (warp0)
        if (tid < CHN) {
            float3 v = qrot(qw0, qx, qy, qz, make_float3(e_vx, e_vy, e_vz));
            float ttv = sfield[tid];
            float3 u = { sfield[CHN + 3 * tid + 0], sfield[CHN + 3 * tid + 1], sfield[CHN + 3 * tid + 2] };
            float3 cr = { v.y * u.z - v.z * u.y, v.z * u.x - v.x * u.z, v.x * u.y - v.y * u.x };
            float lvx = e_al * e_s * u.x + e_bl * ttv * v.x + e_el * cr.x;
            float lvy = e_al * e_s * u.y + e_bl * ttv * v.y + e_el * cr.y;
            float lvz = e_al * e_s * u.z + e_bl * ttv * v.z + e_el * cr.z;
            float avx = e_aa * e_s * u.x + e_ba * ttv * v.x + e_ea * cr.x;
            float avy = e_aa * e_s * u.y + e_ba * ttv * v.y + e_ea * cr.y;
            float avz = e_aa * e_s * u.z + e_ba * ttv * v.z + e_ea * cr.z;
#pragma unroll
            for (int o = 16; o > 0; o >>= 1) {
                lvx += __shfl_down_sync(0xffffffffu, lvx, o);
                lvy += __shfl_down_sync(0xffffffffu, lvy, o);
                lvz += __shfl_down_sync(0xffffffffu, lvz, o);
                avx += __shfl_down_sync(0xffffffffu, avx, o);
                avy += __shfl_down_sync(0xffffffffu, avy, o);
                avz += __shfl_down_sync(0xffffffffu, avz, o);
            }
            if (tid == 0) {
                float3 lv = qrot(qw0, -qx, -qy, -qz, make_float3(lvx, lvy, lvz));
                float3 av = qrot(qw0, -qx, -qy, -qz, make_float3(avx, avy, avz));
                float3 orb = { qc0.y * lv.z - qc0.z * lv.y,
                               qc0.z * lv.x - qc0.x * lv.z,
                               qc0.x * lv.y - qc0.y * lv.x };
                const float inv_s2 = 0.70710678118654752440f;
                float* pp = &g_partial[(t * NQ + qi) * 6];
                pp[0] = e_w * (orb.x + av.x * inv_s2);
                pp[1] = e_w * (orb.y + av.y * inv_s2);
                pp[2] = e_w * (orb.z + av.z * inv_s2);
                pp[3] = e_w * lv.x;
                pp[4] = e_w * lv.y;
                pp[5] = e_w * lv.z;
            }
        }
        __syncthreads();
    }
}

// ---- deterministic final reduction over queries ------------------------------
__global__ void k_reduce(float* __restrict__ out) {
    int t = blockIdx.x, tid = threadIdx.x;
    int lane = tid & 31, wid = tid >> 5;
    float a[6];
    const float* pp = &g_partial[(t * NQ + tid) * 6];
#pragma unroll
    for (int j = 0; j < 6; j++) a[j] = pp[j];
#pragma unroll
    for (int j = 0; j < 6; j++) {
        for (int o = 16; o > 0; o >>= 1)
            a[j] += __shfl_down_sync(0xffffffffu, a[j], o);
    }
    __shared__ float sw[8][6];
    if (lane == 0) {
#pragma unroll
        for (int j = 0; j < 6; j++) sw[wid][j] = a[j];
    }
    __syncthreads();
    if (tid == 0) {
        float r[6] = {0, 0, 0, 0, 0, 0};
        for (int w2 = 0; w2 < 8; w2++)
            for (int j = 0; j < 6; j++) r[j] += sw[w2][j];
        out[t * 3 + 0] = r[0];
        out[t * 3 + 1] = r[1];
        out[t * 3 + 2] = r[2];
        out[NT * 3 + t * 3 + 0] = r[3];
        out[NT * 3 + t * 3 + 1] = r[4];
        out[NT * 3 + t * 3 + 2] = r[5];
    }
}

extern "C" void kernel_launch(void* const* d_in, const int* in_sizes, int n_in,
                              void* d_out, int out_size) {
    const float* T      = (const float*)d_in[0];
    const float* qwgt   = (const float*)d_in[1];
    const float* qfeat  = (const float*)d_in[2];
    const float* qcoord = (const float*)d_in[3];
    const float* nfeat  = (const float*)d_in[4];
    const float* ncoord = (const float*)d_in[5];
    const float* temb   = (const float*)d_in[6];
    const float* Wext   = (const float*)d_in[7];
    const float* Wrbf   = (const float*)d_in[8];
    const float* Wtime  = (const float*)d_in[9];
    const float* wp_lin = (const float*)d_in[10];
    const float* Wv_lin = (const float*)d_in[12];
    const float* wp_ang = (const float*)d_in[13];
    const float* Wv_ang = (const float*)d_in[15];
    const int*   qbatch = (const int*)d_in[16];
    const int*   nbatch = (const int*)d_in[17];
    float* out = (float*)d_out;

    k_pre<<<NNODE / 16 + 1, DD>>>(nfeat, Wext, temb, Wtime, nbatch,
                                  wp_lin, Wv_lin, wp_ang, Wv_ang);
    k_main<<<dim3(NQ, NTG), 256>>>(T, qwgt, qfeat, qcoord, ncoord, Wrbf, qbatch);
    k_reduce<<<NT, NQ>>>(out);
}